// round 4
// baseline (speedup 1.0000x reference)
#include <cuda_runtime.h>
#include <math.h>

#define N_NODES  100000
#define N_EDGES  1000000
#define DIM      64
#define EDIM     32
#define HID      128
#define NLAYERS  4
#define NGRAPHS  64
#define CATDIM   160

// ---------------- device scratch (no allocs allowed) ----------------
__device__ float g_h[N_NODES * DIM];          // 25.6 MB node features
__device__ float g_hd[N_NODES * HID];         // 51.2 MB  h @ W1[0:64] + b1
__device__ float g_hs[N_NODES * HID];         // 51.2 MB  h @ W1[64:128]
__device__ float g_agg[N_NODES * DIM];        // 25.6 MB segment-sum accumulator
__device__ float g_ea[(size_t)N_EDGES * EDIM];// 128 MB edge attributes
__device__ float g_psum[NGRAPHS * DIM];
__device__ float g_pcnt[NGRAPHS];

// ---------------- kernels ----------------
__global__ void k_zero() {
    int idx = blockIdx.x * blockDim.x + threadIdx.x;
    if (idx < N_NODES * DIM) g_agg[idx] = 0.f;
    if (idx < NGRAPHS * DIM) g_psum[idx] = 0.f;
    if (idx < NGRAPHS)       g_pcnt[idx] = 0.f;
}

__global__ void k_embed(const int* __restrict__ atoms, const float* __restrict__ emb) {
    int idx = blockIdx.x * blockDim.x + threadIdx.x;
    if (idx >= N_NODES * DIM) return;
    int n = idx >> 6, d = idx & 63;
    g_h[idx] = emb[atoms[n] * DIM + d];
}

__global__ void k_edge_attr(const int* __restrict__ ei, const float* __restrict__ coords,
                            const int* __restrict__ isr, const float* __restrict__ sub) {
    int e = blockIdx.x * blockDim.x + threadIdx.x;
    if (e >= N_EDGES) return;
    int s = ei[e], d = ei[N_EDGES + e];
    float dx = coords[3*s]   - coords[3*d];
    float dy = coords[3*s+1] - coords[3*d+1];
    float dz = coords[3*s+2] - coords[3*d+2];
    float dist = sqrtf(dx*dx + dy*dy + dz*dz);
    float out[EDIM];
    #pragma unroll
    for (int g = 0; g < 16; g++) {
        float t = dist - (float)g * (5.0f / 15.0f);
        out[g] = __expf(-4.5f * t * t);
    }
    int kind = (isr[s] != isr[d]) ? 1 : 0;
    #pragma unroll
    for (int j = 0; j < 16; j++) out[16 + j] = sub[kind * 16 + j];
    float4* op = (float4*)&g_ea[(size_t)e * EDIM];
    #pragma unroll
    for (int q = 0; q < 8; q++) op[q] = ((float4*)out)[q];
}

// hd[n][c] = b1[c] + sum_k h[n][k]*W1[k][c]  (threads 0..127, c=tid)
// hs[n][c] =          sum_k h[n][k]*W1[64+k][c] (threads 128..255)
// 4 nodes per iteration share each W1 smem load.
__global__ void k_node_lin(const float* __restrict__ W1, const float* __restrict__ b1, int layer) {
    extern __shared__ float sm[];
    float* sW1 = sm;            // [128][128] = rows 0..127 of W1[layer]
    float* sh  = sm + HID*HID;  // [4][64]
    const float* W1l = W1 + (size_t)layer * CATDIM * HID;
    for (int i = threadIdx.x; i < HID * HID; i += blockDim.x) sW1[i] = W1l[i];
    int c    = threadIdx.x & 127;
    int half = threadIdx.x >> 7;
    float bias = half ? 0.f : __ldg(&b1[layer * HID + c]);
    float* outbuf = half ? g_hs : g_hd;
    const float* wbase = sW1 + half * (DIM * HID);
    __syncthreads();
    for (int tile = blockIdx.x; tile * 4 < N_NODES; tile += gridDim.x) {
        int base = tile * 4;
        for (int i = threadIdx.x; i < 4 * DIM; i += blockDim.x)
            sh[i] = g_h[base * DIM + i];
        __syncthreads();
        float acc0 = bias, acc1 = bias, acc2 = bias, acc3 = bias;
        #pragma unroll 8
        for (int k = 0; k < DIM; k++) {
            float w = wbase[k * HID + c];
            acc0 = fmaf(sh[k],       w, acc0);
            acc1 = fmaf(sh[64 + k],  w, acc1);
            acc2 = fmaf(sh[128 + k], w, acc2);
            acc3 = fmaf(sh[192 + k], w, acc3);
        }
        outbuf[(size_t)(base + 0) * HID + c] = acc0;
        outbuf[(size_t)(base + 1) * HID + c] = acc1;
        outbuf[(size_t)(base + 2) * HID + c] = acc2;
        outbuf[(size_t)(base + 3) * HID + c] = acc3;
        __syncthreads();
    }
}

// warp per 4-edge batch: pre = hd[dst]+hs[src]+ea@W1e ; t=silu(pre) ; msg=t@W2+b2 ; atomic agg
__global__ void k_edge_msg(const int* __restrict__ ei,
                           const float* __restrict__ W1,
                           const float* __restrict__ W2,
                           const float* __restrict__ b2, int layer) {
    extern __shared__ float sm[];
    float*  sW1e = sm;                    // [32][128]
    float2* sW2  = (float2*)(sm + 32 * HID); // [128][32] packed (d, d+32)
    const float* W1e = W1 + (size_t)layer * CATDIM * HID + (size_t)(2 * DIM) * HID;
    for (int i = threadIdx.x; i < 32 * HID; i += blockDim.x) sW1e[i] = W1e[i];
    const float* W2l = W2 + (size_t)layer * HID * DIM;
    for (int i = threadIdx.x; i < HID * 32; i += blockDim.x) {
        int k = i >> 5, d = i & 31;
        sW2[i] = make_float2(W2l[k * DIM + d], W2l[k * DIM + d + 32]);
    }
    __syncthreads();
    int lane = threadIdx.x & 31;
    float b2a = __ldg(&b2[layer * DIM + lane]);
    float b2b = __ldg(&b2[layer * DIM + lane + 32]);
    int warpId = blockIdx.x * (blockDim.x >> 5) + (threadIdx.x >> 5);
    int nW = gridDim.x * (blockDim.x >> 5);
    for (int base = warpId * 4; base < N_EDGES; base += nW * 4) {
        int dstv[4]; float a[4]; float pre[4][4];
        #pragma unroll
        for (int i = 0; i < 4; i++) {
            int e = base + i;
            int s = ei[e]; int d = ei[N_EDGES + e];
            dstv[i] = d;
            a[i] = g_ea[(size_t)e * EDIM + lane];
            float4 p = *(const float4*)&g_hd[(size_t)d * HID + lane * 4];
            float4 q = *(const float4*)&g_hs[(size_t)s * HID + lane * 4];
            pre[i][0] = p.x + q.x; pre[i][1] = p.y + q.y;
            pre[i][2] = p.z + q.z; pre[i][3] = p.w + q.w;
        }
        #pragma unroll 4
        for (int j = 0; j < 32; j++) {
            float4 wv = *(const float4*)&sW1e[j * HID + lane * 4];
            #pragma unroll
            for (int i = 0; i < 4; i++) {
                float aj = __shfl_sync(0xffffffffu, a[i], j);
                pre[i][0] = fmaf(aj, wv.x, pre[i][0]);
                pre[i][1] = fmaf(aj, wv.y, pre[i][1]);
                pre[i][2] = fmaf(aj, wv.z, pre[i][2]);
                pre[i][3] = fmaf(aj, wv.w, pre[i][3]);
            }
        }
        float t[4][4];
        #pragma unroll
        for (int i = 0; i < 4; i++) {
            #pragma unroll
            for (int m = 0; m < 4; m++) {
                float x = pre[i][m];
                t[i][m] = __fdividef(x, 1.0f + __expf(-x));  // silu
            }
        }
        float acc[4][2];
        #pragma unroll
        for (int i = 0; i < 4; i++) { acc[i][0] = b2a; acc[i][1] = b2b; }
        #pragma unroll 2
        for (int sl = 0; sl < 32; sl++) {
            #pragma unroll
            for (int m = 0; m < 4; m++) {
                float2 wv = sW2[(sl * 4 + m) * 32 + lane];
                #pragma unroll
                for (int i = 0; i < 4; i++) {
                    float tb = __shfl_sync(0xffffffffu, t[i][m], sl);
                    acc[i][0] = fmaf(tb, wv.x, acc[i][0]);
                    acc[i][1] = fmaf(tb, wv.y, acc[i][1]);
                }
            }
        }
        #pragma unroll
        for (int i = 0; i < 4; i++) {
            atomicAdd(&g_agg[(size_t)dstv[i] * DIM + lane],      acc[i][0]);
            atomicAdd(&g_agg[(size_t)dstv[i] * DIM + lane + 32], acc[i][1]);
        }
    }
}

__global__ void k_update() {  // h = relu(h+agg); re-zero agg for next layer
    int idx = blockIdx.x * blockDim.x + threadIdx.x;
    if (idx >= N_NODES * DIM) return;
    float v = g_h[idx] + g_agg[idx];
    g_h[idx] = fmaxf(v, 0.f);
    g_agg[idx] = 0.f;
}

__global__ void k_pool(const int* __restrict__ bids) {
    int idx = blockIdx.x * blockDim.x + threadIdx.x;
    if (idx >= N_NODES * DIM) return;
    int n = idx >> 6, d = idx & 63;
    int b = bids[n];
    atomicAdd(&g_psum[b * DIM + d], g_h[idx]);
    if (d == 0) atomicAdd(&g_pcnt[b], 1.f);
}

__global__ void k_out(const float* __restrict__ fcw, const float* __restrict__ fcb,
                      float* __restrict__ out) {
    int g = threadIdx.x;
    if (g >= NGRAPHS) return;
    float s = 0.f;
    #pragma unroll
    for (int d = 0; d < DIM; d++) s += g_psum[g * DIM + d] * fcw[d];
    out[g] = s / fmaxf(g_pcnt[g], 1.f) + fcb[0];
}

// ---------------- launch ----------------
extern "C" void kernel_launch(void* const* d_in, const int* in_sizes, int n_in,
                              void* d_out, int out_size) {
    const int*   atoms  = (const int*)d_in[0];
    const int*   ei     = (const int*)d_in[1];
    const float* coords = (const float*)d_in[2];
    const int*   isr    = (const int*)d_in[3];
    const int*   bids   = (const int*)d_in[4];
    const float* emb    = (const float*)d_in[5];
    const float* sub    = (const float*)d_in[6];
    const float* W1     = (const float*)d_in[7];
    const float* b1     = (const float*)d_in[8];
    const float* W2     = (const float*)d_in[9];
    const float* b2     = (const float*)d_in[10];
    const float* fcw    = (const float*)d_in[11];
    const float* fcb    = (const float*)d_in[12];
    float* out = (float*)d_out;

    const int NL_SMEM = (HID * HID + 4 * DIM) * (int)sizeof(float);   // 66560 B
    const int EM_SMEM = (32 * HID + HID * 64) * (int)sizeof(float);   // 49152 B
    cudaFuncSetAttribute(k_node_lin, cudaFuncAttributeMaxDynamicSharedMemorySize, NL_SMEM);
    cudaFuncSetAttribute(k_edge_msg, cudaFuncAttributeMaxDynamicSharedMemorySize, EM_SMEM);

    k_zero<<<25000, 256>>>();
    k_embed<<<25000, 256>>>(atoms, emb);
    k_edge_attr<<<(N_EDGES + 127) / 128, 128>>>(ei, coords, isr, sub);
    for (int l = 0; l < NLAYERS; l++) {
        k_node_lin<<<1250, 256, NL_SMEM>>>(W1, b1, l);
        k_edge_msg<<<1184, 256, EM_SMEM>>>(ei, W1, W2, b2, l);
        k_update<<<25000, 256>>>();
    }
    k_pool<<<25000, 256>>>(bids);
    k_out<<<1, 64>>>(fcw, fcb, out);
}

// round 5
// speedup vs baseline: 1.2002x; 1.2002x over previous
#include <cuda_runtime.h>
#include <math.h>

#define N_NODES  100000
#define N_EDGES  1000000
#define DIM      64
#define EDIM     32
#define HID      128
#define NLAYERS  4
#define NGRAPHS  64
#define CATDIM   160
#define TABN     4096
#define DRANGE   8.0f
#define ICHUNK   64

// ---------------- device scratch (no allocs allowed) ----------------
__device__ float g_h[N_NODES * DIM];           // 25.6 MB node features
__device__ float g_hd[N_NODES * HID];          // 51.2 MB  h @ W1[0:64] + b1
__device__ float g_hs[N_NODES * HID];          // 51.2 MB  h @ W1[64:128]
__device__ float g_agg[N_NODES * DIM];         // 25.6 MB segment-sum accumulator
__device__ int4  g_epack[N_EDGES];             // 16 MB  {src, dst, idx<<1|kind, frac bits}
__device__ float g_tab[NLAYERS * 2 * TABN * HID]; // 16.8 MB edge-attr projection table
__device__ float g_psum[NGRAPHS * DIM];
__device__ float g_pcnt[NGRAPHS];

// ---------------- kernels ----------------
__global__ void k_zero() {
    int idx = blockIdx.x * blockDim.x + threadIdx.x;
    if (idx < N_NODES * DIM) g_agg[idx] = 0.f;
    if (idx < NGRAPHS * DIM) g_psum[idx] = 0.f;
    if (idx < NGRAPHS)       g_pcnt[idx] = 0.f;
}

__global__ void k_embed(const int* __restrict__ atoms, const float* __restrict__ emb) {
    int idx = blockIdx.x * blockDim.x + threadIdx.x;
    if (idx >= N_NODES * DIM) return;
    int n = idx >> 6, d = idx & 63;
    g_h[idx] = emb[atoms[n] * DIM + d];
}

// Build per-(layer,kind) lookup table: tab[l][kind][i][c] =
//   sum_g exp(-4.5(d_i-off_g)^2) * W1[l][128+g][c]  +  sum_j sub[kind][j] * W1[l][144+j][c]
__global__ void k_tab(const float* __restrict__ W1, const float* __restrict__ sub) {
    __shared__ float sW[32 * HID];
    __shared__ float srbf[16];
    int l  = blockIdx.x / (TABN / ICHUNK);
    int i0 = (blockIdx.x % (TABN / ICHUNK)) * ICHUNK;
    int c  = threadIdx.x;
    const float* W1e = W1 + (size_t)l * CATDIM * HID + (size_t)(2 * DIM) * HID;
    for (int i = c; i < 32 * HID; i += blockDim.x) sW[i] = W1e[i];
    __syncthreads();
    // kind-term (exact, independent of i)
    float ks0 = 0.f, ks1 = 0.f;
    #pragma unroll
    for (int j = 0; j < 16; j++) {
        float w = sW[(16 + j) * HID + c];
        ks0 = fmaf(__ldg(&sub[j]),      w, ks0);
        ks1 = fmaf(__ldg(&sub[16 + j]), w, ks1);
    }
    for (int ii = 0; ii < ICHUNK; ii++) {
        int i = i0 + ii;
        float d = (float)i * (DRANGE / (float)(TABN - 1));
        if (c < 16) {
            float t = d - (float)c * (5.0f / 15.0f);
            srbf[c] = __expf(-4.5f * t * t);
        }
        __syncthreads();
        float acc = 0.f;
        #pragma unroll
        for (int g = 0; g < 16; g++) acc = fmaf(srbf[g], sW[g * HID + c], acc);
        size_t base = (((size_t)l * 2) * TABN + i) * HID + c;
        g_tab[base]              = acc + ks0;
        g_tab[base + (size_t)TABN * HID] = acc + ks1;
        __syncthreads();
    }
}

// Precompute per-edge metadata once: src, dst, table index|kind, lerp fraction.
__global__ void k_pack(const int* __restrict__ ei, const float* __restrict__ coords,
                       const int* __restrict__ isr) {
    int e = blockIdx.x * blockDim.x + threadIdx.x;
    if (e >= N_EDGES) return;
    int s = ei[e], d = ei[N_EDGES + e];
    float dx = coords[3*s]   - coords[3*d];
    float dy = coords[3*s+1] - coords[3*d+1];
    float dz = coords[3*s+2] - coords[3*d+2];
    float dist = sqrtf(dx*dx + dy*dy + dz*dz);
    float u = fminf(dist * ((float)(TABN - 1) / DRANGE), (float)TABN - 1.001f);
    int idx = (int)u;
    float frac = u - (float)idx;
    int kind = (isr[s] != isr[d]) ? 1 : 0;
    g_epack[e] = make_int4(s, d, (idx << 1) | kind, __float_as_int(frac));
}

// hd[n][c] = b1[c] + sum_k h[n][k]*W1[k][c]   (threads 0..127, c=tid)
// hs[n][c] =         sum_k h[n][k]*W1[64+k][c] (threads 128..255)
__global__ void k_node_lin(const float* __restrict__ W1, const float* __restrict__ b1, int layer) {
    extern __shared__ float sm[];
    float* sW1 = sm;            // [128][128]
    float* sh  = sm + HID*HID;  // [4][64]
    const float* W1l = W1 + (size_t)layer * CATDIM * HID;
    for (int i = threadIdx.x; i < HID * HID; i += blockDim.x) sW1[i] = W1l[i];
    int c    = threadIdx.x & 127;
    int half = threadIdx.x >> 7;
    float bias = half ? 0.f : __ldg(&b1[layer * HID + c]);
    float* outbuf = half ? g_hs : g_hd;
    const float* wbase = sW1 + half * (DIM * HID);
    __syncthreads();
    for (int tile = blockIdx.x; tile * 4 < N_NODES; tile += gridDim.x) {
        int base = tile * 4;
        for (int i = threadIdx.x; i < 4 * DIM; i += blockDim.x)
            sh[i] = g_h[base * DIM + i];
        __syncthreads();
        float acc0 = bias, acc1 = bias, acc2 = bias, acc3 = bias;
        #pragma unroll
        for (int k = 0; k < DIM; k += 4) {
            float w0 = wbase[(k + 0) * HID + c];
            float w1 = wbase[(k + 1) * HID + c];
            float w2 = wbase[(k + 2) * HID + c];
            float w3 = wbase[(k + 3) * HID + c];
            float4 a = *(const float4*)&sh[k];
            float4 b = *(const float4*)&sh[64 + k];
            float4 e = *(const float4*)&sh[128 + k];
            float4 f = *(const float4*)&sh[192 + k];
            acc0 = fmaf(a.x, w0, acc0); acc0 = fmaf(a.y, w1, acc0);
            acc0 = fmaf(a.z, w2, acc0); acc0 = fmaf(a.w, w3, acc0);
            acc1 = fmaf(b.x, w0, acc1); acc1 = fmaf(b.y, w1, acc1);
            acc1 = fmaf(b.z, w2, acc1); acc1 = fmaf(b.w, w3, acc1);
            acc2 = fmaf(e.x, w0, acc2); acc2 = fmaf(e.y, w1, acc2);
            acc2 = fmaf(e.z, w2, acc2); acc2 = fmaf(e.w, w3, acc2);
            acc3 = fmaf(f.x, w0, acc3); acc3 = fmaf(f.y, w1, acc3);
            acc3 = fmaf(f.z, w2, acc3); acc3 = fmaf(f.w, w3, acc3);
        }
        outbuf[(size_t)(base + 0) * HID + c] = acc0;
        outbuf[(size_t)(base + 1) * HID + c] = acc1;
        outbuf[(size_t)(base + 2) * HID + c] = acc2;
        outbuf[(size_t)(base + 3) * HID + c] = acc3;
        __syncthreads();
    }
}

// warp per 4-edge batch:
//   pre = hd[dst] + hs[src] + lerp(tab[layer][kind], dist)   (table replaces ea@W1e)
//   t = silu(pre) ; msg = t@W2 + b2 ; atomic agg at dst
__global__ void k_edge_msg(const float* __restrict__ W2,
                           const float* __restrict__ b2, int layer) {
    extern __shared__ float sm[];
    float2* sW2 = (float2*)sm;   // [128][32] packed (d, d+32)
    const float* W2l = W2 + (size_t)layer * HID * DIM;
    for (int i = threadIdx.x; i < HID * 32; i += blockDim.x) {
        int k = i >> 5, d = i & 31;
        sW2[i] = make_float2(W2l[k * DIM + d], W2l[k * DIM + d + 32]);
    }
    __syncthreads();
    int lane = threadIdx.x & 31;
    float b2a = __ldg(&b2[layer * DIM + lane]);
    float b2b = __ldg(&b2[layer * DIM + lane + 32]);
    const float* tabL = g_tab + (size_t)layer * 2 * TABN * HID;
    int warpId = blockIdx.x * (blockDim.x >> 5) + (threadIdx.x >> 5);
    int nW = gridDim.x * (blockDim.x >> 5);
    for (int base = warpId * 4; base < N_EDGES; base += nW * 4) {
        int dstv[4]; float pre[4][4];
        #pragma unroll
        for (int i = 0; i < 4; i++) {
            int4 ep = g_epack[base + i];
            dstv[i] = ep.y;
            float4 p = *(const float4*)&g_hd[(size_t)ep.y * HID + lane * 4];
            float4 q = *(const float4*)&g_hs[(size_t)ep.x * HID + lane * 4];
            const float* trow = tabL + ((size_t)(ep.z & 1) * TABN + (ep.z >> 1)) * HID + lane * 4;
            float4 t0 = *(const float4*)trow;
            float4 t1 = *(const float4*)(trow + HID);
            float f = __int_as_float(ep.w);
            pre[i][0] = fmaf(f, t1.x - t0.x, p.x + q.x + t0.x);
            pre[i][1] = fmaf(f, t1.y - t0.y, p.y + q.y + t0.y);
            pre[i][2] = fmaf(f, t1.z - t0.z, p.z + q.z + t0.z);
            pre[i][3] = fmaf(f, t1.w - t0.w, p.w + q.w + t0.w);
        }
        float t[4][4];
        #pragma unroll
        for (int i = 0; i < 4; i++) {
            #pragma unroll
            for (int m = 0; m < 4; m++) {
                float x = pre[i][m];
                t[i][m] = __fdividef(x, 1.0f + __expf(-x));  // silu
            }
        }
        float acc[4][2];
        #pragma unroll
        for (int i = 0; i < 4; i++) { acc[i][0] = b2a; acc[i][1] = b2b; }
        #pragma unroll 2
        for (int sl = 0; sl < 32; sl++) {
            #pragma unroll
            for (int m = 0; m < 4; m++) {
                float2 wv = sW2[(sl * 4 + m) * 32 + lane];
                #pragma unroll
                for (int i = 0; i < 4; i++) {
                    float tb = __shfl_sync(0xffffffffu, t[i][m], sl);
                    acc[i][0] = fmaf(tb, wv.x, acc[i][0]);
                    acc[i][1] = fmaf(tb, wv.y, acc[i][1]);
                }
            }
        }
        #pragma unroll
        for (int i = 0; i < 4; i++) {
            atomicAdd(&g_agg[(size_t)dstv[i] * DIM + lane],      acc[i][0]);
            atomicAdd(&g_agg[(size_t)dstv[i] * DIM + lane + 32], acc[i][1]);
        }
    }
}

__global__ void k_update() {  // h = relu(h+agg); re-zero agg for next layer
    int idx = blockIdx.x * blockDim.x + threadIdx.x;
    if (idx >= N_NODES * DIM) return;
    float v = g_h[idx] + g_agg[idx];
    g_h[idx] = fmaxf(v, 0.f);
    g_agg[idx] = 0.f;
}

__global__ void k_pool(const int* __restrict__ bids) {
    int idx = blockIdx.x * blockDim.x + threadIdx.x;
    if (idx >= N_NODES * DIM) return;
    int n = idx >> 6, d = idx & 63;
    int b = bids[n];
    atomicAdd(&g_psum[b * DIM + d], g_h[idx]);
    if (d == 0) atomicAdd(&g_pcnt[b], 1.f);
}

__global__ void k_out(const float* __restrict__ fcw, const float* __restrict__ fcb,
                      float* __restrict__ out) {
    int g = threadIdx.x;
    if (g >= NGRAPHS) return;
    float s = 0.f;
    #pragma unroll
    for (int d = 0; d < DIM; d++) s += g_psum[g * DIM + d] * fcw[d];
    out[g] = s / fmaxf(g_pcnt[g], 1.f) + fcb[0];
}

// ---------------- launch ----------------
extern "C" void kernel_launch(void* const* d_in, const int* in_sizes, int n_in,
                              void* d_out, int out_size) {
    const int*   atoms  = (const int*)d_in[0];
    const int*   ei     = (const int*)d_in[1];
    const float* coords = (const float*)d_in[2];
    const int*   isr    = (const int*)d_in[3];
    const int*   bids   = (const int*)d_in[4];
    const float* emb    = (const float*)d_in[5];
    const float* sub    = (const float*)d_in[6];
    const float* W1     = (const float*)d_in[7];
    const float* b1     = (const float*)d_in[8];
    const float* W2     = (const float*)d_in[9];
    const float* b2     = (const float*)d_in[10];
    const float* fcw    = (const float*)d_in[11];
    const float* fcb    = (const float*)d_in[12];
    float* out = (float*)d_out;

    const int NL_SMEM = (HID * HID + 4 * DIM) * (int)sizeof(float);   // 66560 B
    const int EM_SMEM = (HID * 64) * (int)sizeof(float);              // 32768 B
    cudaFuncSetAttribute(k_node_lin, cudaFuncAttributeMaxDynamicSharedMemorySize, NL_SMEM);

    k_zero<<<25000, 256>>>();
    k_embed<<<25000, 256>>>(atoms, emb);
    k_tab<<<NLAYERS * (TABN / ICHUNK), 128>>>(W1, sub);
    k_pack<<<(N_EDGES + 255) / 256, 256>>>(ei, coords, isr);
    for (int l = 0; l < NLAYERS; l++) {
        k_node_lin<<<1250, 256, NL_SMEM>>>(W1, b1, l);
        k_edge_msg<<<1184, 256, EM_SMEM>>>(W2, b2, l);
        k_update<<<25000, 256>>>();
    }
    k_pool<<<25000, 256>>>(bids);
    k_out<<<1, 64>>>(fcw, fcb, out);
}